// round 11
// baseline (speedup 1.0000x reference)
#include <cuda_runtime.h>

#define F_IN   512
#define H_DIM  16
#define C_OUT  7
#define NMAX   100000
#define EMAX   3200000
#define TOTMAX (NMAX + EMAX)
#define CHUNK  512
#define NCMAX  ((NMAX + CHUNK - 1) / CHUNK)
#define DMAX   2048

// -------- scratch (static device globals; no runtime allocation) --------
static __device__ float g_h0[NMAX * H_DIM];
static __device__ float g_h1[NMAX * H_DIM];
static __device__ float g_invnA[NMAX];
static __device__ float g_invnB[NMAX];
static __device__ int   g_counts[NMAX];
static __device__ int   g_cursor[NMAX];
static __device__ int   g_off[NMAX + 1];
static __device__ int   g_csr[TOTMAX];
static __device__ int   g_csums[NCMAX];
static __device__ int   g_dhist[DMAX];
static __device__ int   g_dcur[DMAX];
static __device__ int   g_perm[NMAX];

// packed f32x2 FMA: d = a*b + d (two fp32 lanes per instruction; PTX-only form)
__device__ __forceinline__ void fma2(unsigned long long& d,
                                     unsigned long long a, unsigned long long b)
{
    asm("fma.rn.f32x2 %0, %1, %2, %0;" : "+l"(d) : "l"(a), "l"(b));
}

__device__ __forceinline__ float unpack_sum(unsigned long long p)
{
    float lo = __uint_as_float((unsigned int)(p & 0xffffffffu));
    float hi = __uint_as_float((unsigned int)(p >> 32));
    return lo + hi;
}

// ======================= lin1: h = relu(x @ W1^T + b1), fused ||h|| ==========
__global__ void k_lin1(const float* __restrict__ x, const float* __restrict__ W1,
                       const float* __restrict__ b1, float* __restrict__ h,
                       float* __restrict__ invn, int N)
{
    __shared__ float4 Ws[H_DIM * 129];
    const int tid = threadIdx.x;
    const float4* W14 = (const float4*)W1;
    for (int i = tid; i < H_DIM * 128; i += blockDim.x) {
        int k = i >> 7, j = i & 127;
        Ws[k * 129 + j] = W14[k * 128 + j];
    }
    __syncthreads();

    const int warp = tid >> 5, lane = tid & 31;
    const int k = lane & 15, slot = lane >> 4;
    const int row0 = (blockIdx.x * 8 + warp) * 8 + slot * 4;

    const int r0 = min(row0 + 0, N - 1);
    const int r1 = min(row0 + 1, N - 1);
    const int r2 = min(row0 + 2, N - 1);
    const int r3 = min(row0 + 3, N - 1);

    const float4* x4 = (const float4*)x;
    const float4* p0 = x4 + (size_t)r0 * 128;
    const float4* p1 = x4 + (size_t)r1 * 128;
    const float4* p2 = x4 + (size_t)r2 * 128;
    const float4* p3 = x4 + (size_t)r3 * 128;

    unsigned long long a0l = 0ull, a0h = 0ull, a1l = 0ull, a1h = 0ull;
    unsigned long long a2l = 0ull, a2h = 0ull, a3l = 0ull, a3h = 0ull;

    #pragma unroll 4
    for (int j = 0; j < 128; j++) {
        const float4 w = Ws[k * 129 + j];
        const ulonglong2 ww = *reinterpret_cast<const ulonglong2*>(&w);
        float4 v; ulonglong2 vv;
        v = p0[j]; vv = *reinterpret_cast<const ulonglong2*>(&v);
        fma2(a0l, vv.x, ww.x); fma2(a0h, vv.y, ww.y);
        v = p1[j]; vv = *reinterpret_cast<const ulonglong2*>(&v);
        fma2(a1l, vv.x, ww.x); fma2(a1h, vv.y, ww.y);
        v = p2[j]; vv = *reinterpret_cast<const ulonglong2*>(&v);
        fma2(a2l, vv.x, ww.x); fma2(a2h, vv.y, ww.y);
        v = p3[j]; vv = *reinterpret_cast<const ulonglong2*>(&v);
        fma2(a3l, vv.x, ww.x); fma2(a3h, vv.y, ww.y);
    }
    const float bk = b1[k];
    const float v0 = fmaxf(unpack_sum(a0l) + unpack_sum(a0h) + bk, 0.f);
    const float v1 = fmaxf(unpack_sum(a1l) + unpack_sum(a1h) + bk, 0.f);
    const float v2 = fmaxf(unpack_sum(a2l) + unpack_sum(a2h) + bk, 0.f);
    const float v3 = fmaxf(unpack_sum(a3l) + unpack_sum(a3h) + bk, 0.f);

    if (row0 + 0 < N) h[(row0 + 0) * H_DIM + k] = v0;
    if (row0 + 1 < N) h[(row0 + 1) * H_DIM + k] = v1;
    if (row0 + 2 < N) h[(row0 + 2) * H_DIM + k] = v2;
    if (row0 + 3 < N) h[(row0 + 3) * H_DIM + k] = v3;

    float s0 = v0 * v0, s1 = v1 * v1, s2 = v2 * v2, s3 = v3 * v3;
    #pragma unroll
    for (int o = 1; o < 16; o <<= 1) {
        s0 += __shfl_xor_sync(0xffffffffu, s0, o);
        s1 += __shfl_xor_sync(0xffffffffu, s1, o);
        s2 += __shfl_xor_sync(0xffffffffu, s2, o);
        s3 += __shfl_xor_sync(0xffffffffu, s3, o);
    }
    if (k == 0) {
        if (row0 + 0 < N) invn[row0 + 0] = 1.0f / fmaxf(sqrtf(s0), 1e-12f);
        if (row0 + 1 < N) invn[row0 + 1] = 1.0f / fmaxf(sqrtf(s1), 1e-12f);
        if (row0 + 2 < N) invn[row0 + 2] = 1.0f / fmaxf(sqrtf(s2), 1e-12f);
        if (row0 + 3 < N) invn[row0 + 3] = 1.0f / fmaxf(sqrtf(s3), 1e-12f);
    }
}

// ======================= CSR build (dst-grouped, incl. self-loops) ===========
__global__ void k_count_init(int N)
{
    int i = blockIdx.x * blockDim.x + threadIdx.x;
    if (i < N) g_counts[i] = 1;   // self-loop
    if (i < DMAX) g_dhist[i] = 0;
}

__global__ void k_count(const int* __restrict__ ei, int E)
{
    int t = blockIdx.x * blockDim.x + threadIdx.x;
    int e = t * 4;
    if (e + 3 < E) {
        int4 d = *(const int4*)(ei + E + e);
        atomicAdd(&g_counts[d.x], 1);
        atomicAdd(&g_counts[d.y], 1);
        atomicAdd(&g_counts[d.z], 1);
        atomicAdd(&g_counts[d.w], 1);
    } else {
        for (int j = e; j < E; j++) atomicAdd(&g_counts[ei[E + j]], 1);
    }
}

__global__ void k_csum(int N)
{
    const int c = blockIdx.x;
    const int tid = threadIdx.x;           // 256 threads
    const int i = c * CHUNK + tid;
    int s = 0;
    if (i < N) s = g_counts[i];
    if (i + 256 < N && tid + 256 < CHUNK) s += g_counts[i + 256];
    #pragma unroll
    for (int o = 16; o > 0; o >>= 1) s += __shfl_xor_sync(0xffffffffu, s, o);
    __shared__ int ws[8];
    if ((tid & 31) == 0) ws[tid >> 5] = s;
    __syncthreads();
    if (tid < 8) {
        int v = ws[tid];
        #pragma unroll
        for (int o = 4; o > 0; o >>= 1) v += __shfl_xor_sync(0x000000ffu, v, o);
        if (tid == 0) g_csums[c] = v;
    }
}

__global__ void k_scan(int NC)
{
    const int tid = threadIdx.x;           // 256 threads
    const int lane = tid & 31, w = tid >> 5;
    int v = (tid < NC) ? g_csums[tid] : 0;
    int x = v;
    #pragma unroll
    for (int o = 1; o < 32; o <<= 1) {
        int t = __shfl_up_sync(0xffffffffu, x, o);
        if (lane >= o) x += t;
    }
    __shared__ int wsum[8];
    if (lane == 31) wsum[w] = x;
    __syncthreads();
    if (tid < 8) {
        int y = wsum[tid];
        #pragma unroll
        for (int o = 1; o < 8; o <<= 1) {
            int t = __shfl_up_sync(0x000000ffu, y, o);
            if (tid >= o) y += t;
        }
        wsum[tid] = y;
    }
    __syncthreads();
    const int incl = x + (w ? wsum[w - 1] : 0);
    if (tid < NC) g_csums[tid] = incl - v;   // exclusive
}

__global__ void k_cscan(int N)
{
    const int c = blockIdx.x;
    const int tid = threadIdx.x;           // 512 threads
    const int i = c * CHUNK + tid;
    const int lane = tid & 31, w = tid >> 5;   // 16 warps
    const int v = (i < N) ? g_counts[i] : 0;
    int x = v;
    #pragma unroll
    for (int o = 1; o < 32; o <<= 1) {
        int t = __shfl_up_sync(0xffffffffu, x, o);
        if (lane >= o) x += t;
    }
    __shared__ int wsum[16];
    if (lane == 31) wsum[w] = x;
    __syncthreads();
    if (tid < 16) {
        int y = wsum[tid];
        #pragma unroll
        for (int o = 1; o < 16; o <<= 1) {
            int t = __shfl_up_sync(0x0000ffffu, y, o);
            if (tid >= o) y += t;
        }
        wsum[tid] = y;
    }
    __syncthreads();
    const int excl = x - v + (w ? wsum[w - 1] : 0);
    const int off = g_csums[c] + excl;
    if (i < N) {
        g_off[i] = off;
        g_cursor[i] = off;
        if (i == N - 1) g_off[N] = off + v;
    }
}

__global__ void k_scatter(const int* __restrict__ ei, int E, int N)
{
    int t = blockIdx.x * blockDim.x + threadIdx.x;
    if (t >= E + N) return;
    int s, d;
    if (t < E) { s = ei[t]; d = ei[E + t]; }
    else       { s = t - E; d = s; }
    int pos = atomicAdd(&g_cursor[d], 1);
    g_csr[pos] = s;
}

// ======================= degree-sorted node permutation ======================
__global__ void k_dhist(int N)
{
    int i = blockIdx.x * blockDim.x + threadIdx.x;
    if (i < N) atomicAdd(&g_dhist[min(g_counts[i], DMAX - 1)], 1);
}

// one warp: exclusive scan over DMAX bins (each lane owns a 64-bin segment)
__global__ void k_dscan()
{
    const int lane = threadIdx.x;       // 32 threads
    const int base = lane * (DMAX / 32);
    int s = 0;
    for (int j = 0; j < DMAX / 32; j++) s += g_dhist[base + j];
    int x = s;
    #pragma unroll
    for (int o = 1; o < 32; o <<= 1) {
        int t = __shfl_up_sync(0xffffffffu, x, o);
        if (lane >= o) x += t;
    }
    int run = x - s;                    // exclusive prefix of this segment
    for (int j = 0; j < DMAX / 32; j++) {
        int t = g_dhist[base + j];
        g_dcur[base + j] = run;
        run += t;
    }
}

__global__ void k_dscatter(int N)
{
    int i = blockIdx.x * blockDim.x + threadIdx.x;
    if (i >= N) return;
    int pos = atomicAdd(&g_dcur[min(g_counts[i], DMAX - 1)], 1);
    g_perm[pos] = i;
}

// ======================= fused AGNN layer (pair-cooperative, perm, pipe-2) ===
// 8 lanes per dst node = 4 edge-slots x 2 lanes; node chosen via degree-sorted
// permutation so all octets in a warp have similar degree. Each lane loads
// HALF the 64B src row; depth-2 software pipeline keeps the NEXT edge's row
// gather in flight during the current edge's math. One pair shfl for the dot;
// no softmax max (|logit| <= |beta|). Last layer fuses classify+log_softmax.
__global__ void k_agnn(const float* __restrict__ hin, float* __restrict__ hout,
                       const float* __restrict__ invn_in, float* __restrict__ invn_out,
                       const float* __restrict__ betap, int use_beta, int N,
                       int last, const float* __restrict__ W2,
                       const float* __restrict__ b2, float* __restrict__ out)
{
    const int gid = blockIdx.x * blockDim.x + threadIdx.x;
    int nidx = gid >> 3;
    const int o8   = gid & 7;        // position within octet
    const int slot = o8 >> 1;        // 0..3  edge slot
    const int p    = o8 & 1;         // 0..1  row half
    const unsigned pair_mask = 3u << ((threadIdx.x & 31) & ~1);
    const bool store_ok = (nidx < N);
    if (nidx >= N) nidx = N - 1;     // clamp: keep lanes alive for shuffles
    const int node = g_perm[nidx];

    const float beta = use_beta ? betap[0] : 1.0f;
    const float4* __restrict__ h4 = (const float4*)hin;

    // this lane's half of the dst row
    float hd[8];
    {
        float4 a = h4[node * 4 + p * 2 + 0];
        float4 b = h4[node * 4 + p * 2 + 1];
        hd[0] = a.x; hd[1] = a.y; hd[2] = a.z; hd[3] = a.w;
        hd[4] = b.x; hd[5] = b.y; hd[6] = b.z; hd[7] = b.w;
    }
    const float cd = beta * invn_in[node];
    const int beg = g_off[node], end = g_off[node + 1];

    float s = 0.f;
    float n[8];
    #pragma unroll
    for (int q = 0; q < 8; q++) n[q] = 0.f;

    int i = beg + slot;
    if (i < end) {
        // stage A: first edge fully in flight
        int   srcA = g_csr[i];
        float siA  = invn_in[srcA];
        float4 a0 = h4[srcA * 4 + p * 2 + 0];
        float4 a1 = h4[srcA * 4 + p * 2 + 1];
        for (i += 4; i < end; i += 4) {
            // stage B: issue next edge's loads before touching A's data
            const int   srcB = g_csr[i];
            const float siB  = invn_in[srcB];
            const float4 b0 = h4[srcB * 4 + p * 2 + 0];
            const float4 b1 = h4[srcB * 4 + p * 2 + 1];
            // compute on A
            float pd = fmaf(hd[0], a0.x, fmaf(hd[1], a0.y, fmaf(hd[2], a0.z,
                       fmaf(hd[3], a0.w, fmaf(hd[4], a1.x, fmaf(hd[5], a1.y,
                       fmaf(hd[6], a1.z, hd[7] * a1.w)))))));
            pd += __shfl_xor_sync(pair_mask, pd, 1);
            const float w = __expf(cd * siA * pd);
            s += w;
            n[0] = fmaf(w, a0.x, n[0]); n[1] = fmaf(w, a0.y, n[1]);
            n[2] = fmaf(w, a0.z, n[2]); n[3] = fmaf(w, a0.w, n[3]);
            n[4] = fmaf(w, a1.x, n[4]); n[5] = fmaf(w, a1.y, n[5]);
            n[6] = fmaf(w, a1.z, n[6]); n[7] = fmaf(w, a1.w, n[7]);
            a0 = b0; a1 = b1; siA = siB;
        }
        // drain stage A
        float pd = fmaf(hd[0], a0.x, fmaf(hd[1], a0.y, fmaf(hd[2], a0.z,
                   fmaf(hd[3], a0.w, fmaf(hd[4], a1.x, fmaf(hd[5], a1.y,
                   fmaf(hd[6], a1.z, hd[7] * a1.w)))))));
        pd += __shfl_xor_sync(pair_mask, pd, 1);
        const float w = __expf(cd * siA * pd);
        s += w;
        n[0] = fmaf(w, a0.x, n[0]); n[1] = fmaf(w, a0.y, n[1]);
        n[2] = fmaf(w, a0.z, n[2]); n[3] = fmaf(w, a0.w, n[3]);
        n[4] = fmaf(w, a1.x, n[4]); n[5] = fmaf(w, a1.y, n[5]);
        n[6] = fmaf(w, a1.z, n[6]); n[7] = fmaf(w, a1.w, n[7]);
    }

    // combine across the 4 slots (preserves half p); s becomes the full sum
    #pragma unroll
    for (int o = 2; o <= 4; o <<= 1) {
        s += __shfl_xor_sync(0xffffffffu, s, o);
        #pragma unroll
        for (int q = 0; q < 8; q++)
            n[q] += __shfl_xor_sync(0xffffffffu, n[q], o);
    }

    if (slot == 0) {   // lanes o8==0 (half 0) and o8==1 (half 1)
        const float is = 1.0f / s;
        float v[8];
        float ss = 0.f;
        #pragma unroll
        for (int q = 0; q < 8; q++) { v[q] = n[q] * is; ss = fmaf(v[q], v[q], ss); }

        if (!last) {
            if (store_ok) {
                float4* o4 = (float4*)hout;
                o4[node * 4 + p * 2 + 0] = make_float4(v[0], v[1], v[2], v[3]);
                o4[node * 4 + p * 2 + 1] = make_float4(v[4], v[5], v[6], v[7]);
            }
            ss += __shfl_xor_sync(pair_mask, ss, 1);
            if (p == 0 && store_ok)
                invn_out[node] = 1.0f / fmaxf(sqrtf(ss), 1e-12f);
        } else {
            // fused classify + log_softmax: partial logits over this half
            float lg[C_OUT];
            #pragma unroll
            for (int c = 0; c < C_OUT; c++) {
                float acc = 0.f;
                #pragma unroll
                for (int q = 0; q < 8; q++)
                    acc = fmaf(v[q], W2[c * H_DIM + p * 8 + q], acc);
                lg[c] = acc;
            }
            #pragma unroll
            for (int c = 0; c < C_OUT; c++)
                lg[c] += __shfl_xor_sync(pair_mask, lg[c], 1);
            if (p == 0 && store_ok) {
                #pragma unroll
                for (int c = 0; c < C_OUT; c++) lg[c] += b2[c];
                float mx = lg[0];
                #pragma unroll
                for (int c = 1; c < C_OUT; c++) mx = fmaxf(mx, lg[c]);
                float ssum = 0.f;
                #pragma unroll
                for (int c = 0; c < C_OUT; c++) ssum += __expf(lg[c] - mx);
                const float lse = mx + __logf(ssum);
                #pragma unroll
                for (int c = 0; c < C_OUT; c++) out[node * C_OUT + c] = lg[c] - lse;
            }
        }
    }
}

// ======================= launch ==============================================
extern "C" void kernel_launch(void* const* d_in, const int* in_sizes, int n_in,
                              void* d_out, int out_size)
{
    const float* x     = (const float*)d_in[0];
    const int*   ei    = (const int*)d_in[1];
    const float* W1    = (const float*)d_in[2];
    const float* b1    = (const float*)d_in[3];
    const float* beta2 = (const float*)d_in[4];
    const float* beta3 = (const float*)d_in[5];
    const float* beta4 = (const float*)d_in[6];
    const float* W2    = (const float*)d_in[7];
    const float* b2    = (const float*)d_in[8];
    float* out = (float*)d_out;

    const int N = in_sizes[0] / F_IN;
    const int E = in_sizes[1] / 2;
    const int NC = (N + CHUNK - 1) / CHUNK;

    float *hA, *hB, *inA, *inB;
    cudaGetSymbolAddress((void**)&hA, g_h0);
    cudaGetSymbolAddress((void**)&hB, g_h1);
    cudaGetSymbolAddress((void**)&inA, g_invnA);
    cudaGetSymbolAddress((void**)&inB, g_invnB);

    // lin1 (+ invn of h)
    k_lin1<<<(N + 63) / 64, 256>>>(x, W1, b1, hA, inA, N);

    // CSR build
    k_count_init<<<(max(N, DMAX) + 255) / 256, 256>>>(N);
    k_count<<<((E + 3) / 4 + 255) / 256, 256>>>(ei, E);
    k_csum<<<NC, 256>>>(N);
    k_scan<<<1, 256>>>(NC);
    k_cscan<<<NC, 512>>>(N);
    k_scatter<<<(E + N + 255) / 256, 256>>>(ei, E, N);

    // degree-sorted permutation (uses g_counts; independent of csr content)
    k_dhist<<<(N + 255) / 256, 256>>>(N);
    k_dscan<<<1, 32>>>();
    k_dscatter<<<(N + 255) / 256, 256>>>(N);

    // 4 AGNN layers (layer 0: beta fixed at 1.0; layer 3 fuses classify)
    const float* betas[4] = {nullptr, beta2, beta3, beta4};
    float* cur = hA; float* nxt = hB;
    float* icur = inA; float* inxt = inB;
    for (int l = 0; l < 4; l++) {
        const int last = (l == 3);
        k_agnn<<<(N * 8 + 255) / 256, 256>>>(cur, nxt, icur, inxt,
                                             betas[l], l > 0 ? 1 : 0, N,
                                             last, W2, b2, out);
        float* t = cur; cur = nxt; nxt = t;
        t = icur; icur = inxt; inxt = t;
    }
}

// round 12
// speedup vs baseline: 1.1054x; 1.1054x over previous
#include <cuda_runtime.h>

#define F_IN   512
#define H_DIM  16
#define C_OUT  7
#define NMAX   100000
#define EMAX   3200000
#define TOTMAX (NMAX + EMAX)
#define CHUNK  512
#define NCMAX  ((NMAX + CHUNK - 1) / CHUNK)

// -------- scratch (static device globals; no runtime allocation) --------
static __device__ float g_h0[NMAX * H_DIM];
static __device__ float g_h1[NMAX * H_DIM];
static __device__ float g_invnA[NMAX];
static __device__ float g_invnB[NMAX];
static __device__ int   g_counts[NMAX];
static __device__ int   g_cursor[NMAX];
static __device__ int   g_off[NMAX + 1];
static __device__ int   g_csr[TOTMAX];
static __device__ int   g_csums[NCMAX];

// packed f32x2 FMA: d = a*b + d (two fp32 lanes per instruction; PTX-only form)
__device__ __forceinline__ void fma2(unsigned long long& d,
                                     unsigned long long a, unsigned long long b)
{
    asm("fma.rn.f32x2 %0, %1, %2, %0;" : "+l"(d) : "l"(a), "l"(b));
}

__device__ __forceinline__ float unpack_sum(unsigned long long p)
{
    float lo = __uint_as_float((unsigned int)(p & 0xffffffffu));
    float hi = __uint_as_float((unsigned int)(p >> 32));
    return lo + hi;
}

// ======================= lin1: h = relu(x @ W1^T + b1), fused ||h|| ==========
__global__ void k_lin1(const float* __restrict__ x, const float* __restrict__ W1,
                       const float* __restrict__ b1, float* __restrict__ h,
                       float* __restrict__ invn, int N)
{
    __shared__ float4 Ws[H_DIM * 129];
    const int tid = threadIdx.x;
    const float4* W14 = (const float4*)W1;
    for (int i = tid; i < H_DIM * 128; i += blockDim.x) {
        int k = i >> 7, j = i & 127;
        Ws[k * 129 + j] = W14[k * 128 + j];
    }
    __syncthreads();

    const int warp = tid >> 5, lane = tid & 31;
    const int k = lane & 15, slot = lane >> 4;
    const int row0 = (blockIdx.x * 8 + warp) * 8 + slot * 4;

    const int r0 = min(row0 + 0, N - 1);
    const int r1 = min(row0 + 1, N - 1);
    const int r2 = min(row0 + 2, N - 1);
    const int r3 = min(row0 + 3, N - 1);

    const float4* x4 = (const float4*)x;
    const float4* p0 = x4 + (size_t)r0 * 128;
    const float4* p1 = x4 + (size_t)r1 * 128;
    const float4* p2 = x4 + (size_t)r2 * 128;
    const float4* p3 = x4 + (size_t)r3 * 128;

    unsigned long long a0l = 0ull, a0h = 0ull, a1l = 0ull, a1h = 0ull;
    unsigned long long a2l = 0ull, a2h = 0ull, a3l = 0ull, a3h = 0ull;

    #pragma unroll 4
    for (int j = 0; j < 128; j++) {
        const float4 w = Ws[k * 129 + j];
        const ulonglong2 ww = *reinterpret_cast<const ulonglong2*>(&w);
        float4 v; ulonglong2 vv;
        v = p0[j]; vv = *reinterpret_cast<const ulonglong2*>(&v);
        fma2(a0l, vv.x, ww.x); fma2(a0h, vv.y, ww.y);
        v = p1[j]; vv = *reinterpret_cast<const ulonglong2*>(&v);
        fma2(a1l, vv.x, ww.x); fma2(a1h, vv.y, ww.y);
        v = p2[j]; vv = *reinterpret_cast<const ulonglong2*>(&v);
        fma2(a2l, vv.x, ww.x); fma2(a2h, vv.y, ww.y);
        v = p3[j]; vv = *reinterpret_cast<const ulonglong2*>(&v);
        fma2(a3l, vv.x, ww.x); fma2(a3h, vv.y, ww.y);
    }
    const float bk = b1[k];
    const float v0 = fmaxf(unpack_sum(a0l) + unpack_sum(a0h) + bk, 0.f);
    const float v1 = fmaxf(unpack_sum(a1l) + unpack_sum(a1h) + bk, 0.f);
    const float v2 = fmaxf(unpack_sum(a2l) + unpack_sum(a2h) + bk, 0.f);
    const float v3 = fmaxf(unpack_sum(a3l) + unpack_sum(a3h) + bk, 0.f);

    if (row0 + 0 < N) h[(row0 + 0) * H_DIM + k] = v0;
    if (row0 + 1 < N) h[(row0 + 1) * H_DIM + k] = v1;
    if (row0 + 2 < N) h[(row0 + 2) * H_DIM + k] = v2;
    if (row0 + 3 < N) h[(row0 + 3) * H_DIM + k] = v3;

    float s0 = v0 * v0, s1 = v1 * v1, s2 = v2 * v2, s3 = v3 * v3;
    #pragma unroll
    for (int o = 1; o < 16; o <<= 1) {
        s0 += __shfl_xor_sync(0xffffffffu, s0, o);
        s1 += __shfl_xor_sync(0xffffffffu, s1, o);
        s2 += __shfl_xor_sync(0xffffffffu, s2, o);
        s3 += __shfl_xor_sync(0xffffffffu, s3, o);
    }
    if (k == 0) {
        if (row0 + 0 < N) invn[row0 + 0] = 1.0f / fmaxf(sqrtf(s0), 1e-12f);
        if (row0 + 1 < N) invn[row0 + 1] = 1.0f / fmaxf(sqrtf(s1), 1e-12f);
        if (row0 + 2 < N) invn[row0 + 2] = 1.0f / fmaxf(sqrtf(s2), 1e-12f);
        if (row0 + 3 < N) invn[row0 + 3] = 1.0f / fmaxf(sqrtf(s3), 1e-12f);
    }
}

// ======================= CSR build (dst-grouped, incl. self-loops) ===========
__global__ void k_count_init(int N)
{
    int i = blockIdx.x * blockDim.x + threadIdx.x;
    if (i < N) g_counts[i] = 1;   // self-loop
}

__global__ void k_count(const int* __restrict__ ei, int E)
{
    int t = blockIdx.x * blockDim.x + threadIdx.x;
    int e = t * 4;
    if (e + 3 < E) {
        int4 d = *(const int4*)(ei + E + e);
        atomicAdd(&g_counts[d.x], 1);
        atomicAdd(&g_counts[d.y], 1);
        atomicAdd(&g_counts[d.z], 1);
        atomicAdd(&g_counts[d.w], 1);
    } else {
        for (int j = e; j < E; j++) atomicAdd(&g_counts[ei[E + j]], 1);
    }
}

__global__ void k_csum(int N)
{
    const int c = blockIdx.x;
    const int tid = threadIdx.x;           // 256 threads
    const int i = c * CHUNK + tid;
    int s = 0;
    if (i < N) s = g_counts[i];
    if (i + 256 < N && tid + 256 < CHUNK) s += g_counts[i + 256];
    #pragma unroll
    for (int o = 16; o > 0; o >>= 1) s += __shfl_xor_sync(0xffffffffu, s, o);
    __shared__ int ws[8];
    if ((tid & 31) == 0) ws[tid >> 5] = s;
    __syncthreads();
    if (tid < 8) {
        int v = ws[tid];
        #pragma unroll
        for (int o = 4; o > 0; o >>= 1) v += __shfl_xor_sync(0x000000ffu, v, o);
        if (tid == 0) g_csums[c] = v;
    }
}

__global__ void k_scan(int NC)
{
    const int tid = threadIdx.x;           // 256 threads
    const int lane = tid & 31, w = tid >> 5;
    int v = (tid < NC) ? g_csums[tid] : 0;
    int x = v;
    #pragma unroll
    for (int o = 1; o < 32; o <<= 1) {
        int t = __shfl_up_sync(0xffffffffu, x, o);
        if (lane >= o) x += t;
    }
    __shared__ int wsum[8];
    if (lane == 31) wsum[w] = x;
    __syncthreads();
    if (tid < 8) {
        int y = wsum[tid];
        #pragma unroll
        for (int o = 1; o < 8; o <<= 1) {
            int t = __shfl_up_sync(0x000000ffu, y, o);
            if (tid >= o) y += t;
        }
        wsum[tid] = y;
    }
    __syncthreads();
    const int incl = x + (w ? wsum[w - 1] : 0);
    if (tid < NC) g_csums[tid] = incl - v;   // exclusive
}

__global__ void k_cscan(int N)
{
    const int c = blockIdx.x;
    const int tid = threadIdx.x;           // 512 threads
    const int i = c * CHUNK + tid;
    const int lane = tid & 31, w = tid >> 5;   // 16 warps
    const int v = (i < N) ? g_counts[i] : 0;
    int x = v;
    #pragma unroll
    for (int o = 1; o < 32; o <<= 1) {
        int t = __shfl_up_sync(0xffffffffu, x, o);
        if (lane >= o) x += t;
    }
    __shared__ int wsum[16];
    if (lane == 31) wsum[w] = x;
    __syncthreads();
    if (tid < 16) {
        int y = wsum[tid];
        #pragma unroll
        for (int o = 1; o < 16; o <<= 1) {
            int t = __shfl_up_sync(0x0000ffffu, y, o);
            if (tid >= o) y += t;
        }
        wsum[tid] = y;
    }
    __syncthreads();
    const int excl = x - v + (w ? wsum[w - 1] : 0);
    const int off = g_csums[c] + excl;
    if (i < N) {
        g_off[i] = off;
        g_cursor[i] = off;
        if (i == N - 1) g_off[N] = off + v;
    }
}

__global__ void k_scatter(const int* __restrict__ ei, int E, int N)
{
    int t = blockIdx.x * blockDim.x + threadIdx.x;
    if (t >= E + N) return;
    int s, d;
    if (t < E) { s = ei[t]; d = ei[E + t]; }
    else       { s = t - E; d = s; }
    int pos = atomicAdd(&g_cursor[d], 1);
    g_csr[pos] = s;
}

// ======================= fused AGNN layer (pair-cooperative, pipe-2) =========
// 8 lanes per dst node = 4 edge-slots x 2 lanes (natural node order — NO
// degree permutation; sorted order loses to grid-tail imbalance + scattered
// dst traffic, measured R11). Each lane loads HALF the 64B src row; depth-2
// software pipeline keeps the NEXT edge's row gather in flight during the
// current edge's math. One pair shfl for the dot; no softmax max (|logit| <=
// |beta|). Last layer fuses classify + log_softmax.
__global__ void k_agnn(const float* __restrict__ hin, float* __restrict__ hout,
                       const float* __restrict__ invn_in, float* __restrict__ invn_out,
                       const float* __restrict__ betap, int use_beta, int N,
                       int last, const float* __restrict__ W2,
                       const float* __restrict__ b2, float* __restrict__ out)
{
    const int gid = blockIdx.x * blockDim.x + threadIdx.x;
    int node = gid >> 3;
    const int o8   = gid & 7;        // position within octet
    const int slot = o8 >> 1;        // 0..3  edge slot
    const int p    = o8 & 1;         // 0..1  row half
    const unsigned pair_mask = 3u << ((threadIdx.x & 31) & ~1);
    const bool store_ok = (node < N);
    if (node >= N) node = N - 1;     // clamp: keep lanes alive for shuffles

    const float beta = use_beta ? betap[0] : 1.0f;
    const float4* __restrict__ h4 = (const float4*)hin;

    // this lane's half of the dst row
    float hd[8];
    {
        float4 a = h4[node * 4 + p * 2 + 0];
        float4 b = h4[node * 4 + p * 2 + 1];
        hd[0] = a.x; hd[1] = a.y; hd[2] = a.z; hd[3] = a.w;
        hd[4] = b.x; hd[5] = b.y; hd[6] = b.z; hd[7] = b.w;
    }
    const float cd = beta * invn_in[node];
    const int beg = g_off[node], end = g_off[node + 1];

    float s = 0.f;
    float n[8];
    #pragma unroll
    for (int q = 0; q < 8; q++) n[q] = 0.f;

    int i = beg + slot;
    if (i < end) {
        // stage A: first edge fully in flight
        int   srcA = g_csr[i];
        float siA  = invn_in[srcA];
        float4 a0 = h4[srcA * 4 + p * 2 + 0];
        float4 a1 = h4[srcA * 4 + p * 2 + 1];
        for (i += 4; i < end; i += 4) {
            // stage B: issue next edge's loads before touching A's data
            const int   srcB = g_csr[i];
            const float siB  = invn_in[srcB];
            const float4 b0 = h4[srcB * 4 + p * 2 + 0];
            const float4 b1 = h4[srcB * 4 + p * 2 + 1];
            // compute on A
            float pd = fmaf(hd[0], a0.x, fmaf(hd[1], a0.y, fmaf(hd[2], a0.z,
                       fmaf(hd[3], a0.w, fmaf(hd[4], a1.x, fmaf(hd[5], a1.y,
                       fmaf(hd[6], a1.z, hd[7] * a1.w)))))));
            pd += __shfl_xor_sync(pair_mask, pd, 1);
            const float w = __expf(cd * siA * pd);
            s += w;
            n[0] = fmaf(w, a0.x, n[0]); n[1] = fmaf(w, a0.y, n[1]);
            n[2] = fmaf(w, a0.z, n[2]); n[3] = fmaf(w, a0.w, n[3]);
            n[4] = fmaf(w, a1.x, n[4]); n[5] = fmaf(w, a1.y, n[5]);
            n[6] = fmaf(w, a1.z, n[6]); n[7] = fmaf(w, a1.w, n[7]);
            a0 = b0; a1 = b1; siA = siB;
        }
        // drain stage A
        float pd = fmaf(hd[0], a0.x, fmaf(hd[1], a0.y, fmaf(hd[2], a0.z,
                   fmaf(hd[3], a0.w, fmaf(hd[4], a1.x, fmaf(hd[5], a1.y,
                   fmaf(hd[6], a1.z, hd[7] * a1.w)))))));
        pd += __shfl_xor_sync(pair_mask, pd, 1);
        const float w = __expf(cd * siA * pd);
        s += w;
        n[0] = fmaf(w, a0.x, n[0]); n[1] = fmaf(w, a0.y, n[1]);
        n[2] = fmaf(w, a0.z, n[2]); n[3] = fmaf(w, a0.w, n[3]);
        n[4] = fmaf(w, a1.x, n[4]); n[5] = fmaf(w, a1.y, n[5]);
        n[6] = fmaf(w, a1.z, n[6]); n[7] = fmaf(w, a1.w, n[7]);
    }

    // combine across the 4 slots (preserves half p); s becomes the full sum
    #pragma unroll
    for (int o = 2; o <= 4; o <<= 1) {
        s += __shfl_xor_sync(0xffffffffu, s, o);
        #pragma unroll
        for (int q = 0; q < 8; q++)
            n[q] += __shfl_xor_sync(0xffffffffu, n[q], o);
    }

    if (slot == 0) {   // lanes o8==0 (half 0) and o8==1 (half 1)
        const float is = 1.0f / s;
        float v[8];
        float ss = 0.f;
        #pragma unroll
        for (int q = 0; q < 8; q++) { v[q] = n[q] * is; ss = fmaf(v[q], v[q], ss); }

        if (!last) {
            if (store_ok) {
                float4* o4 = (float4*)hout;
                o4[node * 4 + p * 2 + 0] = make_float4(v[0], v[1], v[2], v[3]);
                o4[node * 4 + p * 2 + 1] = make_float4(v[4], v[5], v[6], v[7]);
            }
            ss += __shfl_xor_sync(pair_mask, ss, 1);
            if (p == 0 && store_ok)
                invn_out[node] = 1.0f / fmaxf(sqrtf(ss), 1e-12f);
        } else {
            // fused classify + log_softmax: partial logits over this half
            float lg[C_OUT];
            #pragma unroll
            for (int c = 0; c < C_OUT; c++) {
                float acc = 0.f;
                #pragma unroll
                for (int q = 0; q < 8; q++)
                    acc = fmaf(v[q], W2[c * H_DIM + p * 8 + q], acc);
                lg[c] = acc;
            }
            #pragma unroll
            for (int c = 0; c < C_OUT; c++)
                lg[c] += __shfl_xor_sync(pair_mask, lg[c], 1);
            if (p == 0 && store_ok) {
                #pragma unroll
                for (int c = 0; c < C_OUT; c++) lg[c] += b2[c];
                float mx = lg[0];
                #pragma unroll
                for (int c = 1; c < C_OUT; c++) mx = fmaxf(mx, lg[c]);
                float ssum = 0.f;
                #pragma unroll
                for (int c = 0; c < C_OUT; c++) ssum += __expf(lg[c] - mx);
                const float lse = mx + __logf(ssum);
                #pragma unroll
                for (int c = 0; c < C_OUT; c++) out[node * C_OUT + c] = lg[c] - lse;
            }
        }
    }
}

// ======================= launch ==============================================
extern "C" void kernel_launch(void* const* d_in, const int* in_sizes, int n_in,
                              void* d_out, int out_size)
{
    const float* x     = (const float*)d_in[0];
    const int*   ei    = (const int*)d_in[1];
    const float* W1    = (const float*)d_in[2];
    const float* b1    = (const float*)d_in[3];
    const float* beta2 = (const float*)d_in[4];
    const float* beta3 = (const float*)d_in[5];
    const float* beta4 = (const float*)d_in[6];
    const float* W2    = (const float*)d_in[7];
    const float* b2    = (const float*)d_in[8];
    float* out = (float*)d_out;

    const int N = in_sizes[0] / F_IN;
    const int E = in_sizes[1] / 2;
    const int NC = (N + CHUNK - 1) / CHUNK;

    float *hA, *hB, *inA, *inB;
    cudaGetSymbolAddress((void**)&hA, g_h0);
    cudaGetSymbolAddress((void**)&hB, g_h1);
    cudaGetSymbolAddress((void**)&inA, g_invnA);
    cudaGetSymbolAddress((void**)&inB, g_invnB);

    // lin1 (+ invn of h)
    k_lin1<<<(N + 63) / 64, 256>>>(x, W1, b1, hA, inA, N);

    // CSR build
    k_count_init<<<(N + 255) / 256, 256>>>(N);
    k_count<<<((E + 3) / 4 + 255) / 256, 256>>>(ei, E);
    k_csum<<<NC, 256>>>(N);
    k_scan<<<1, 256>>>(NC);
    k_cscan<<<NC, 512>>>(N);
    k_scatter<<<(E + N + 255) / 256, 256>>>(ei, E, N);

    // 4 AGNN layers (layer 0: beta fixed at 1.0; layer 3 fuses classify)
    const float* betas[4] = {nullptr, beta2, beta3, beta4};
    float* cur = hA; float* nxt = hB;
    float* icur = inA; float* inxt = inB;
    for (int l = 0; l < 4; l++) {
        const int last = (l == 3);
        k_agnn<<<(N * 8 + 255) / 256, 256>>>(cur, nxt, icur, inxt,
                                             betas[l], l > 0 ? 1 : 0, N,
                                             last, W2, b2, out);
        float* t = cur; cur = nxt; nxt = t;
        t = icur; icur = inxt; inxt = t;
    }
}

// round 13
// speedup vs baseline: 1.1167x; 1.0102x over previous
#include <cuda_runtime.h>

#define F_IN   512
#define H_DIM  16
#define C_OUT  7
#define NMAX   100000
#define EMAX   3200000
#define TOTMAX (NMAX + EMAX)
#define CHUNK  512
#define NCMAX  ((NMAX + CHUNK - 1) / CHUNK)

// -------- scratch (static device globals; no runtime allocation) --------
static __device__ float g_h0[NMAX * H_DIM];
static __device__ float g_h1[NMAX * H_DIM];
static __device__ float g_invnA[NMAX];
static __device__ float g_invnB[NMAX];
static __device__ int   g_counts[NMAX];
static __device__ int   g_cursor[NMAX];
static __device__ int   g_off[NMAX + 1];
static __device__ int   g_csr[TOTMAX];
static __device__ int   g_csums[NCMAX];

// packed f32x2 FMA: d = a*b + d (two fp32 lanes per instruction; PTX-only form)
__device__ __forceinline__ void fma2(unsigned long long& d,
                                     unsigned long long a, unsigned long long b)
{
    asm("fma.rn.f32x2 %0, %1, %2, %0;" : "+l"(d) : "l"(a), "l"(b));
}

__device__ __forceinline__ float unpack_sum(unsigned long long p)
{
    float lo = __uint_as_float((unsigned int)(p & 0xffffffffu));
    float hi = __uint_as_float((unsigned int)(p >> 32));
    return lo + hi;
}

// ======================= lin1: h = relu(x @ W1^T + b1), fused ||h|| ==========
__global__ void k_lin1(const float* __restrict__ x, const float* __restrict__ W1,
                       const float* __restrict__ b1, float* __restrict__ h,
                       float* __restrict__ invn, int N)
{
    __shared__ float4 Ws[H_DIM * 129];
    const int tid = threadIdx.x;
    const float4* W14 = (const float4*)W1;
    for (int i = tid; i < H_DIM * 128; i += blockDim.x) {
        int k = i >> 7, j = i & 127;
        Ws[k * 129 + j] = W14[k * 128 + j];
    }
    __syncthreads();

    const int warp = tid >> 5, lane = tid & 31;
    const int k = lane & 15, slot = lane >> 4;
    const int row0 = (blockIdx.x * 8 + warp) * 8 + slot * 4;

    const int r0 = min(row0 + 0, N - 1);
    const int r1 = min(row0 + 1, N - 1);
    const int r2 = min(row0 + 2, N - 1);
    const int r3 = min(row0 + 3, N - 1);

    const float4* x4 = (const float4*)x;
    const float4* p0 = x4 + (size_t)r0 * 128;
    const float4* p1 = x4 + (size_t)r1 * 128;
    const float4* p2 = x4 + (size_t)r2 * 128;
    const float4* p3 = x4 + (size_t)r3 * 128;

    unsigned long long a0l = 0ull, a0h = 0ull, a1l = 0ull, a1h = 0ull;
    unsigned long long a2l = 0ull, a2h = 0ull, a3l = 0ull, a3h = 0ull;

    #pragma unroll 4
    for (int j = 0; j < 128; j++) {
        const float4 w = Ws[k * 129 + j];
        const ulonglong2 ww = *reinterpret_cast<const ulonglong2*>(&w);
        float4 v; ulonglong2 vv;
        v = p0[j]; vv = *reinterpret_cast<const ulonglong2*>(&v);
        fma2(a0l, vv.x, ww.x); fma2(a0h, vv.y, ww.y);
        v = p1[j]; vv = *reinterpret_cast<const ulonglong2*>(&v);
        fma2(a1l, vv.x, ww.x); fma2(a1h, vv.y, ww.y);
        v = p2[j]; vv = *reinterpret_cast<const ulonglong2*>(&v);
        fma2(a2l, vv.x, ww.x); fma2(a2h, vv.y, ww.y);
        v = p3[j]; vv = *reinterpret_cast<const ulonglong2*>(&v);
        fma2(a3l, vv.x, ww.x); fma2(a3h, vv.y, ww.y);
    }
    const float bk = b1[k];
    const float v0 = fmaxf(unpack_sum(a0l) + unpack_sum(a0h) + bk, 0.f);
    const float v1 = fmaxf(unpack_sum(a1l) + unpack_sum(a1h) + bk, 0.f);
    const float v2 = fmaxf(unpack_sum(a2l) + unpack_sum(a2h) + bk, 0.f);
    const float v3 = fmaxf(unpack_sum(a3l) + unpack_sum(a3h) + bk, 0.f);

    if (row0 + 0 < N) h[(row0 + 0) * H_DIM + k] = v0;
    if (row0 + 1 < N) h[(row0 + 1) * H_DIM + k] = v1;
    if (row0 + 2 < N) h[(row0 + 2) * H_DIM + k] = v2;
    if (row0 + 3 < N) h[(row0 + 3) * H_DIM + k] = v3;

    float s0 = v0 * v0, s1 = v1 * v1, s2 = v2 * v2, s3 = v3 * v3;
    #pragma unroll
    for (int o = 1; o < 16; o <<= 1) {
        s0 += __shfl_xor_sync(0xffffffffu, s0, o);
        s1 += __shfl_xor_sync(0xffffffffu, s1, o);
        s2 += __shfl_xor_sync(0xffffffffu, s2, o);
        s3 += __shfl_xor_sync(0xffffffffu, s3, o);
    }
    if (k == 0) {
        if (row0 + 0 < N) invn[row0 + 0] = 1.0f / fmaxf(sqrtf(s0), 1e-12f);
        if (row0 + 1 < N) invn[row0 + 1] = 1.0f / fmaxf(sqrtf(s1), 1e-12f);
        if (row0 + 2 < N) invn[row0 + 2] = 1.0f / fmaxf(sqrtf(s2), 1e-12f);
        if (row0 + 3 < N) invn[row0 + 3] = 1.0f / fmaxf(sqrtf(s3), 1e-12f);
    }
}

// ======================= CSR build (dst-grouped, incl. self-loops) ===========
__global__ void k_count_init(int N)
{
    int i = blockIdx.x * blockDim.x + threadIdx.x;
    if (i < N) g_counts[i] = 1;   // self-loop
}

__global__ void k_count(const int* __restrict__ ei, int E)
{
    int t = blockIdx.x * blockDim.x + threadIdx.x;
    int e = t * 4;
    if (e + 3 < E) {
        int4 d = *(const int4*)(ei + E + e);
        atomicAdd(&g_counts[d.x], 1);
        atomicAdd(&g_counts[d.y], 1);
        atomicAdd(&g_counts[d.z], 1);
        atomicAdd(&g_counts[d.w], 1);
    } else {
        for (int j = e; j < E; j++) atomicAdd(&g_counts[ei[E + j]], 1);
    }
}

__global__ void k_csum(int N)
{
    const int c = blockIdx.x;
    const int tid = threadIdx.x;           // 256 threads
    const int i = c * CHUNK + tid;
    int s = 0;
    if (i < N) s = g_counts[i];
    if (i + 256 < N && tid + 256 < CHUNK) s += g_counts[i + 256];
    #pragma unroll
    for (int o = 16; o > 0; o >>= 1) s += __shfl_xor_sync(0xffffffffu, s, o);
    __shared__ int ws[8];
    if ((tid & 31) == 0) ws[tid >> 5] = s;
    __syncthreads();
    if (tid < 8) {
        int v = ws[tid];
        #pragma unroll
        for (int o = 4; o > 0; o >>= 1) v += __shfl_xor_sync(0x000000ffu, v, o);
        if (tid == 0) g_csums[c] = v;
    }
}

__global__ void k_scan(int NC)
{
    const int tid = threadIdx.x;           // 256 threads
    const int lane = tid & 31, w = tid >> 5;
    int v = (tid < NC) ? g_csums[tid] : 0;
    int x = v;
    #pragma unroll
    for (int o = 1; o < 32; o <<= 1) {
        int t = __shfl_up_sync(0xffffffffu, x, o);
        if (lane >= o) x += t;
    }
    __shared__ int wsum[8];
    if (lane == 31) wsum[w] = x;
    __syncthreads();
    if (tid < 8) {
        int y = wsum[tid];
        #pragma unroll
        for (int o = 1; o < 8; o <<= 1) {
            int t = __shfl_up_sync(0x000000ffu, y, o);
            if (tid >= o) y += t;
        }
        wsum[tid] = y;
    }
    __syncthreads();
    const int incl = x + (w ? wsum[w - 1] : 0);
    if (tid < NC) g_csums[tid] = incl - v;   // exclusive
}

__global__ void k_cscan(int N)
{
    const int c = blockIdx.x;
    const int tid = threadIdx.x;           // 512 threads
    const int i = c * CHUNK + tid;
    const int lane = tid & 31, w = tid >> 5;   // 16 warps
    const int v = (i < N) ? g_counts[i] : 0;
    int x = v;
    #pragma unroll
    for (int o = 1; o < 32; o <<= 1) {
        int t = __shfl_up_sync(0xffffffffu, x, o);
        if (lane >= o) x += t;
    }
    __shared__ int wsum[16];
    if (lane == 31) wsum[w] = x;
    __syncthreads();
    if (tid < 16) {
        int y = wsum[tid];
        #pragma unroll
        for (int o = 1; o < 16; o <<= 1) {
            int t = __shfl_up_sync(0x0000ffffu, y, o);
            if (tid >= o) y += t;
        }
        wsum[tid] = y;
    }
    __syncthreads();
    const int excl = x - v + (w ? wsum[w - 1] : 0);
    const int off = g_csums[c] + excl;
    if (i < N) {
        g_off[i] = off;
        g_cursor[i] = off;
        if (i == N - 1) g_off[N] = off + v;
    }
}

__global__ void k_scatter(const int* __restrict__ ei, int E, int N)
{
    int t = blockIdx.x * blockDim.x + threadIdx.x;
    if (t >= E + N) return;
    int s, d;
    if (t < E) { s = ei[t]; d = ei[E + t]; }
    else       { s = t - E; d = s; }
    int pos = atomicAdd(&g_cursor[d], 1);
    g_csr[pos] = s;
}

// ======================= fused AGNN layer (pair-coop, dual-edge unroll) ======
// 8 lanes per dst node = 4 edge-slots x 2 lanes, natural node order. Each lane
// loads HALF the 64B src row. Each slot processes TWO edges per iteration
// (i, i+4) with fully independent accumulator sets (s0,n0)/(s1,n1) -> 4 row
// LDG.128 in flight before any dependent math, no stage-copy overhead
// (pipe-2 copies measured -9us regression R12). One pair shfl per edge dot;
// no softmax max (|logit| <= |beta|). Last layer fuses classify+log_softmax.
__global__ void k_agnn(const float* __restrict__ hin, float* __restrict__ hout,
                       const float* __restrict__ invn_in, float* __restrict__ invn_out,
                       const float* __restrict__ betap, int use_beta, int N,
                       int last, const float* __restrict__ W2,
                       const float* __restrict__ b2, float* __restrict__ out)
{
    const int gid = blockIdx.x * blockDim.x + threadIdx.x;
    int node = gid >> 3;
    const int o8   = gid & 7;        // position within octet
    const int slot = o8 >> 1;        // 0..3  edge slot
    const int p    = o8 & 1;         // 0..1  row half
    const unsigned pair_mask = 3u << ((threadIdx.x & 31) & ~1);
    const bool store_ok = (node < N);
    if (node >= N) node = N - 1;     // clamp: keep lanes alive for shuffles

    const float beta = use_beta ? betap[0] : 1.0f;
    const float4* __restrict__ h4 = (const float4*)hin;

    // this lane's half of the dst row
    float hd[8];
    {
        float4 a = h4[node * 4 + p * 2 + 0];
        float4 b = h4[node * 4 + p * 2 + 1];
        hd[0] = a.x; hd[1] = a.y; hd[2] = a.z; hd[3] = a.w;
        hd[4] = b.x; hd[5] = b.y; hd[6] = b.z; hd[7] = b.w;
    }
    const float cd = beta * invn_in[node];
    const int beg = g_off[node], end = g_off[node + 1];

    float sA = 0.f, sB = 0.f;
    float nA[8], nB[8];
    #pragma unroll
    for (int q = 0; q < 8; q++) { nA[q] = 0.f; nB[q] = 0.f; }

    int i = beg + slot;
    // dual-edge main loop: edges i and i+4, independent chains
    for (; i + 4 < end; i += 8) {
        const int   srcA = g_csr[i];
        const int   srcB = g_csr[i + 4];
        const float siA  = invn_in[srcA];
        const float siB  = invn_in[srcB];
        const float4 a0 = h4[srcA * 4 + p * 2 + 0];
        const float4 a1 = h4[srcA * 4 + p * 2 + 1];
        const float4 b0 = h4[srcB * 4 + p * 2 + 0];
        const float4 b1 = h4[srcB * 4 + p * 2 + 1];

        float pdA = fmaf(hd[0], a0.x, fmaf(hd[1], a0.y, fmaf(hd[2], a0.z,
                    fmaf(hd[3], a0.w, fmaf(hd[4], a1.x, fmaf(hd[5], a1.y,
                    fmaf(hd[6], a1.z, hd[7] * a1.w)))))));
        float pdB = fmaf(hd[0], b0.x, fmaf(hd[1], b0.y, fmaf(hd[2], b0.z,
                    fmaf(hd[3], b0.w, fmaf(hd[4], b1.x, fmaf(hd[5], b1.y,
                    fmaf(hd[6], b1.z, hd[7] * b1.w)))))));
        pdA += __shfl_xor_sync(pair_mask, pdA, 1);
        pdB += __shfl_xor_sync(pair_mask, pdB, 1);
        const float wA = __expf(cd * siA * pdA);
        const float wB = __expf(cd * siB * pdB);
        sA += wA; sB += wB;
        nA[0] = fmaf(wA, a0.x, nA[0]); nA[1] = fmaf(wA, a0.y, nA[1]);
        nA[2] = fmaf(wA, a0.z, nA[2]); nA[3] = fmaf(wA, a0.w, nA[3]);
        nA[4] = fmaf(wA, a1.x, nA[4]); nA[5] = fmaf(wA, a1.y, nA[5]);
        nA[6] = fmaf(wA, a1.z, nA[6]); nA[7] = fmaf(wA, a1.w, nA[7]);
        nB[0] = fmaf(wB, b0.x, nB[0]); nB[1] = fmaf(wB, b0.y, nB[1]);
        nB[2] = fmaf(wB, b0.z, nB[2]); nB[3] = fmaf(wB, b0.w, nB[3]);
        nB[4] = fmaf(wB, b1.x, nB[4]); nB[5] = fmaf(wB, b1.y, nB[5]);
        nB[6] = fmaf(wB, b1.z, nB[6]); nB[7] = fmaf(wB, b1.w, nB[7]);
    }
    // remainder: at most one edge for this slot
    if (i < end) {
        const int   srcA = g_csr[i];
        const float siA  = invn_in[srcA];
        const float4 a0 = h4[srcA * 4 + p * 2 + 0];
        const float4 a1 = h4[srcA * 4 + p * 2 + 1];
        float pdA = fmaf(hd[0], a0.x, fmaf(hd[1], a0.y, fmaf(hd[2], a0.z,
                    fmaf(hd[3], a0.w, fmaf(hd[4], a1.x, fmaf(hd[5], a1.y,
                    fmaf(hd[6], a1.z, hd[7] * a1.w)))))));
        pdA += __shfl_xor_sync(pair_mask, pdA, 1);
        const float wA = __expf(cd * siA * pdA);
        sA += wA;
        nA[0] = fmaf(wA, a0.x, nA[0]); nA[1] = fmaf(wA, a0.y, nA[1]);
        nA[2] = fmaf(wA, a0.z, nA[2]); nA[3] = fmaf(wA, a0.w, nA[3]);
        nA[4] = fmaf(wA, a1.x, nA[4]); nA[5] = fmaf(wA, a1.y, nA[5]);
        nA[6] = fmaf(wA, a1.z, nA[6]); nA[7] = fmaf(wA, a1.w, nA[7]);
    }

    // merge dual accumulators
    float s = sA + sB;
    float n[8];
    #pragma unroll
    for (int q = 0; q < 8; q++) n[q] = nA[q] + nB[q];

    // combine across the 4 slots (preserves half p); s becomes the full sum
    #pragma unroll
    for (int o = 2; o <= 4; o <<= 1) {
        s += __shfl_xor_sync(0xffffffffu, s, o);
        #pragma unroll
        for (int q = 0; q < 8; q++)
            n[q] += __shfl_xor_sync(0xffffffffu, n[q], o);
    }

    if (slot == 0) {   // lanes o8==0 (half 0) and o8==1 (half 1)
        const float is = 1.0f / s;
        float v[8];
        float ss = 0.f;
        #pragma unroll
        for (int q = 0; q < 8; q++) { v[q] = n[q] * is; ss = fmaf(v[q], v[q], ss); }

        if (!last) {
            if (store_ok) {
                float4* o4 = (float4*)hout;
                o4[node * 4 + p * 2 + 0] = make_float4(v[0], v[1], v[2], v[3]);
                o4[node * 4 + p * 2 + 1] = make_float4(v[4], v[5], v[6], v[7]);
            }
            ss += __shfl_xor_sync(pair_mask, ss, 1);
            if (p == 0 && store_ok)
                invn_out[node] = 1.0f / fmaxf(sqrtf(ss), 1e-12f);
        } else {
            // fused classify + log_softmax: partial logits over this half
            float lg[C_OUT];
            #pragma unroll
            for (int c = 0; c < C_OUT; c++) {
                float acc = 0.f;
                #pragma unroll
                for (int q = 0; q < 8; q++)
                    acc = fmaf(v[q], W2[c * H_DIM + p * 8 + q], acc);
                lg[c] = acc;
            }
            #pragma unroll
            for (int c = 0; c < C_OUT; c++)
                lg[c] += __shfl_xor_sync(pair_mask, lg[c], 1);
            if (p == 0 && store_ok) {
                #pragma unroll
                for (int c = 0; c < C_OUT; c++) lg[c] += b2[c];
                float mx = lg[0];
                #pragma unroll
                for (int c = 1; c < C_OUT; c++) mx = fmaxf(mx, lg[c]);
                float ssum = 0.f;
                #pragma unroll
                for (int c = 0; c < C_OUT; c++) ssum += __expf(lg[c] - mx);
                const float lse = mx + __logf(ssum);
                #pragma unroll
                for (int c = 0; c < C_OUT; c++) out[node * C_OUT + c] = lg[c] - lse;
            }
        }
    }
}

// ======================= launch ==============================================
extern "C" void kernel_launch(void* const* d_in, const int* in_sizes, int n_in,
                              void* d_out, int out_size)
{
    const float* x     = (const float*)d_in[0];
    const int*   ei    = (const int*)d_in[1];
    const float* W1    = (const float*)d_in[2];
    const float* b1    = (const float*)d_in[3];
    const float* beta2 = (const float*)d_in[4];
    const float* beta3 = (const float*)d_in[5];
    const float* beta4 = (const float*)d_in[6];
    const float* W2    = (const float*)d_in[7];
    const float* b2    = (const float*)d_in[8];
    float* out = (float*)d_out;

    const int N = in_sizes[0] / F_IN;
    const int E = in_sizes[1] / 2;
    const int NC = (N + CHUNK - 1) / CHUNK;

    float *hA, *hB, *inA, *inB;
    cudaGetSymbolAddress((void**)&hA, g_h0);
    cudaGetSymbolAddress((void**)&hB, g_h1);
    cudaGetSymbolAddress((void**)&inA, g_invnA);
    cudaGetSymbolAddress((void**)&inB, g_invnB);

    // lin1 (+ invn of h)
    k_lin1<<<(N + 63) / 64, 256>>>(x, W1, b1, hA, inA, N);

    // CSR build
    k_count_init<<<(N + 255) / 256, 256>>>(N);
    k_count<<<((E + 3) / 4 + 255) / 256, 256>>>(ei, E);
    k_csum<<<NC, 256>>>(N);
    k_scan<<<1, 256>>>(NC);
    k_cscan<<<NC, 512>>>(N);
    k_scatter<<<(E + N + 255) / 256, 256>>>(ei, E, N);

    // 4 AGNN layers (layer 0: beta fixed at 1.0; layer 3 fuses classify)
    const float* betas[4] = {nullptr, beta2, beta3, beta4};
    float* cur = hA; float* nxt = hB;
    float* icur = inA; float* inxt = inB;
    for (int l = 0; l < 4; l++) {
        const int last = (l == 3);
        k_agnn<<<(N * 8 + 255) / 256, 256>>>(cur, nxt, icur, inxt,
                                             betas[l], l > 0 ? 1 : 0, N,
                                             last, W2, b2, out);
        float* t = cur; cur = nxt; nxt = t;
        t = icur; icur = inxt; inxt = t;
    }
}

// round 14
// speedup vs baseline: 1.1808x; 1.0574x over previous
#include <cuda_runtime.h>

#define F_IN   512
#define H_DIM  16
#define C_OUT  7
#define NMAX   100000
#define EMAX   3200000
#define TOTMAX (NMAX + EMAX)
#define CHUNK  512
#define NCMAX  ((NMAX + CHUNK - 1) / CHUNK)

// -------- scratch (static device globals; no runtime allocation) --------
static __device__ float g_h0[NMAX * H_DIM];
static __device__ float g_h1[NMAX * H_DIM];
static __device__ int   g_counts[NMAX];
static __device__ int   g_cursor[NMAX];
static __device__ int   g_off[NMAX + 1];
static __device__ int   g_csr[TOTMAX];
static __device__ int   g_csums[NCMAX];

// packed f32x2 FMA: d = a*b + d (two fp32 lanes per instruction; PTX-only form)
__device__ __forceinline__ void fma2(unsigned long long& d,
                                     unsigned long long a, unsigned long long b)
{
    asm("fma.rn.f32x2 %0, %1, %2, %0;" : "+l"(d) : "l"(a), "l"(b));
}

__device__ __forceinline__ float unpack_sum(unsigned long long p)
{
    float lo = __uint_as_float((unsigned int)(p & 0xffffffffu));
    float hi = __uint_as_float((unsigned int)(p >> 32));
    return lo + hi;
}

// ======================= lin1: h = relu(x @ W1^T + b1) =======================
// (no norm epilogue — AGNN layers compute norms on the fly)
__global__ void k_lin1(const float* __restrict__ x, const float* __restrict__ W1,
                       const float* __restrict__ b1, float* __restrict__ h, int N)
{
    __shared__ float4 Ws[H_DIM * 129];
    const int tid = threadIdx.x;
    const float4* W14 = (const float4*)W1;
    for (int i = tid; i < H_DIM * 128; i += blockDim.x) {
        int k = i >> 7, j = i & 127;
        Ws[k * 129 + j] = W14[k * 128 + j];
    }
    __syncthreads();

    const int warp = tid >> 5, lane = tid & 31;
    const int k = lane & 15, slot = lane >> 4;
    const int row0 = (blockIdx.x * 8 + warp) * 8 + slot * 4;

    const int r0 = min(row0 + 0, N - 1);
    const int r1 = min(row0 + 1, N - 1);
    const int r2 = min(row0 + 2, N - 1);
    const int r3 = min(row0 + 3, N - 1);

    const float4* x4 = (const float4*)x;
    const float4* p0 = x4 + (size_t)r0 * 128;
    const float4* p1 = x4 + (size_t)r1 * 128;
    const float4* p2 = x4 + (size_t)r2 * 128;
    const float4* p3 = x4 + (size_t)r3 * 128;

    unsigned long long a0l = 0ull, a0h = 0ull, a1l = 0ull, a1h = 0ull;
    unsigned long long a2l = 0ull, a2h = 0ull, a3l = 0ull, a3h = 0ull;

    #pragma unroll 4
    for (int j = 0; j < 128; j++) {
        const float4 w = Ws[k * 129 + j];
        const ulonglong2 ww = *reinterpret_cast<const ulonglong2*>(&w);
        float4 v; ulonglong2 vv;
        v = p0[j]; vv = *reinterpret_cast<const ulonglong2*>(&v);
        fma2(a0l, vv.x, ww.x); fma2(a0h, vv.y, ww.y);
        v = p1[j]; vv = *reinterpret_cast<const ulonglong2*>(&v);
        fma2(a1l, vv.x, ww.x); fma2(a1h, vv.y, ww.y);
        v = p2[j]; vv = *reinterpret_cast<const ulonglong2*>(&v);
        fma2(a2l, vv.x, ww.x); fma2(a2h, vv.y, ww.y);
        v = p3[j]; vv = *reinterpret_cast<const ulonglong2*>(&v);
        fma2(a3l, vv.x, ww.x); fma2(a3h, vv.y, ww.y);
    }
    const float bk = b1[k];
    const float v0 = fmaxf(unpack_sum(a0l) + unpack_sum(a0h) + bk, 0.f);
    const float v1 = fmaxf(unpack_sum(a1l) + unpack_sum(a1h) + bk, 0.f);
    const float v2 = fmaxf(unpack_sum(a2l) + unpack_sum(a2h) + bk, 0.f);
    const float v3 = fmaxf(unpack_sum(a3l) + unpack_sum(a3h) + bk, 0.f);

    if (row0 + 0 < N) h[(row0 + 0) * H_DIM + k] = v0;
    if (row0 + 1 < N) h[(row0 + 1) * H_DIM + k] = v1;
    if (row0 + 2 < N) h[(row0 + 2) * H_DIM + k] = v2;
    if (row0 + 3 < N) h[(row0 + 3) * H_DIM + k] = v3;
}

// ======================= CSR build (dst-grouped, incl. self-loops) ===========
__global__ void k_count_init(int N)
{
    int i = blockIdx.x * blockDim.x + threadIdx.x;
    if (i < N) g_counts[i] = 1;   // self-loop
}

__global__ void k_count(const int* __restrict__ ei, int E)
{
    int t = blockIdx.x * blockDim.x + threadIdx.x;
    int e = t * 4;
    if (e + 3 < E) {
        int4 d = *(const int4*)(ei + E + e);
        atomicAdd(&g_counts[d.x], 1);
        atomicAdd(&g_counts[d.y], 1);
        atomicAdd(&g_counts[d.z], 1);
        atomicAdd(&g_counts[d.w], 1);
    } else {
        for (int j = e; j < E; j++) atomicAdd(&g_counts[ei[E + j]], 1);
    }
}

__global__ void k_csum(int N)
{
    const int c = blockIdx.x;
    const int tid = threadIdx.x;           // 256 threads
    const int i = c * CHUNK + tid;
    int s = 0;
    if (i < N) s = g_counts[i];
    if (i + 256 < N && tid + 256 < CHUNK) s += g_counts[i + 256];
    #pragma unroll
    for (int o = 16; o > 0; o >>= 1) s += __shfl_xor_sync(0xffffffffu, s, o);
    __shared__ int ws[8];
    if ((tid & 31) == 0) ws[tid >> 5] = s;
    __syncthreads();
    if (tid < 8) {
        int v = ws[tid];
        #pragma unroll
        for (int o = 4; o > 0; o >>= 1) v += __shfl_xor_sync(0x000000ffu, v, o);
        if (tid == 0) g_csums[c] = v;
    }
}

__global__ void k_scan(int NC)
{
    const int tid = threadIdx.x;           // 256 threads
    const int lane = tid & 31, w = tid >> 5;
    int v = (tid < NC) ? g_csums[tid] : 0;
    int x = v;
    #pragma unroll
    for (int o = 1; o < 32; o <<= 1) {
        int t = __shfl_up_sync(0xffffffffu, x, o);
        if (lane >= o) x += t;
    }
    __shared__ int wsum[8];
    if (lane == 31) wsum[w] = x;
    __syncthreads();
    if (tid < 8) {
        int y = wsum[tid];
        #pragma unroll
        for (int o = 1; o < 8; o <<= 1) {
            int t = __shfl_up_sync(0x000000ffu, y, o);
            if (tid >= o) y += t;
        }
        wsum[tid] = y;
    }
    __syncthreads();
    const int incl = x + (w ? wsum[w - 1] : 0);
    if (tid < NC) g_csums[tid] = incl - v;   // exclusive
}

__global__ void k_cscan(int N)
{
    const int c = blockIdx.x;
    const int tid = threadIdx.x;           // 512 threads
    const int i = c * CHUNK + tid;
    const int lane = tid & 31, w = tid >> 5;   // 16 warps
    const int v = (i < N) ? g_counts[i] : 0;
    int x = v;
    #pragma unroll
    for (int o = 1; o < 32; o <<= 1) {
        int t = __shfl_up_sync(0xffffffffu, x, o);
        if (lane >= o) x += t;
    }
    __shared__ int wsum[16];
    if (lane == 31) wsum[w] = x;
    __syncthreads();
    if (tid < 16) {
        int y = wsum[tid];
        #pragma unroll
        for (int o = 1; o < 16; o <<= 1) {
            int t = __shfl_up_sync(0x0000ffffu, y, o);
            if (tid >= o) y += t;
        }
        wsum[tid] = y;
    }
    __syncthreads();
    const int excl = x - v + (w ? wsum[w - 1] : 0);
    const int off = g_csums[c] + excl;
    if (i < N) {
        g_off[i] = off;
        g_cursor[i] = off;
        if (i == N - 1) g_off[N] = off + v;
    }
}

__global__ void k_scatter(const int* __restrict__ ei, int E, int N)
{
    int t = blockIdx.x * blockDim.x + threadIdx.x;
    if (t >= E + N) return;
    int s, d;
    if (t < E) { s = ei[t]; d = ei[E + t]; }
    else       { s = t - E; d = s; }
    int pos = atomicAdd(&g_cursor[d], 1);
    g_csr[pos] = s;
}

// ======================= fused AGNN layer (pair-coop, on-the-fly norms) ======
// L1tex-replay model (R13): each scattered LDG pays ~2.07 cyc per 128B-line
// wavefront; the old invn gather was a full extra wavefront per edge (1/3 of
// the L1 budget). Here src/dst norms are computed IN-REGISTER from the already
// gathered halves: one extra pair shfl + rsqrt per edge (MUFU cost per warp-
// instruction = negligible). 2 wavefronts/edge remain (the two row LDG.128s).
// 8 lanes per dst node = 4 edge-slots x 2 lanes, natural node order, R10 loop
// shape (simple index prefetch; pipe-2/dual-unroll measured worse R12/R13).
// No softmax max (|logit| <= |beta|). Last layer fuses classify+log_softmax.
__global__ void k_agnn(const float* __restrict__ hin, float* __restrict__ hout,
                       const float* __restrict__ betap, int use_beta, int N,
                       int last, const float* __restrict__ W2,
                       const float* __restrict__ b2, float* __restrict__ out)
{
    const int gid = blockIdx.x * blockDim.x + threadIdx.x;
    int node = gid >> 3;
    const int o8   = gid & 7;        // position within octet
    const int slot = o8 >> 1;        // 0..3  edge slot
    const int p    = o8 & 1;         // 0..1  row half
    const unsigned pair_mask = 3u << ((threadIdx.x & 31) & ~1);
    const bool store_ok = (node < N);
    if (node >= N) node = N - 1;     // clamp: keep lanes alive for shuffles

    const float beta = use_beta ? betap[0] : 1.0f;
    const float4* __restrict__ h4 = (const float4*)hin;

    // this lane's half of the dst row + on-the-fly dst inverse norm
    float hd[8];
    {
        float4 a = h4[node * 4 + p * 2 + 0];
        float4 b = h4[node * 4 + p * 2 + 1];
        hd[0] = a.x; hd[1] = a.y; hd[2] = a.z; hd[3] = a.w;
        hd[4] = b.x; hd[5] = b.y; hd[6] = b.z; hd[7] = b.w;
    }
    float sd = 0.f;
    #pragma unroll
    for (int q = 0; q < 8; q++) sd = fmaf(hd[q], hd[q], sd);
    sd += __shfl_xor_sync(pair_mask, sd, 1);
    const float cd = beta * rsqrtf(fmaxf(sd, 1e-24f));

    const int beg = g_off[node], end = g_off[node + 1];

    float s = 0.f;
    float n[8];
    #pragma unroll
    for (int q = 0; q < 8; q++) n[q] = 0.f;

    int i = beg + slot;
    if (i < end) {
        int src = g_csr[i];
        while (i < end) {
            const int csrc = src;
            const float4 a0 = h4[csrc * 4 + p * 2 + 0];
            const float4 a1 = h4[csrc * 4 + p * 2 + 1];
            i += 4;
            if (i < end) src = g_csr[i];   // prefetch next edge's index
            float hs[8];
            hs[0] = a0.x; hs[1] = a0.y; hs[2] = a0.z; hs[3] = a0.w;
            hs[4] = a1.x; hs[5] = a1.y; hs[6] = a1.z; hs[7] = a1.w;
            float pd = 0.f, ps = 0.f;
            #pragma unroll
            for (int q = 0; q < 8; q++) {
                pd = fmaf(hd[q], hs[q], pd);
                ps = fmaf(hs[q], hs[q], ps);
            }
            pd += __shfl_xor_sync(pair_mask, pd, 1);
            ps += __shfl_xor_sync(pair_mask, ps, 1);
            const float w = __expf(cd * rsqrtf(fmaxf(ps, 1e-24f)) * pd);
            s += w;
            #pragma unroll
            for (int q = 0; q < 8; q++) n[q] = fmaf(w, hs[q], n[q]);
        }
    }

    // combine across the 4 slots (preserves half p); s becomes the full sum
    #pragma unroll
    for (int o = 2; o <= 4; o <<= 1) {
        s += __shfl_xor_sync(0xffffffffu, s, o);
        #pragma unroll
        for (int q = 0; q < 8; q++)
            n[q] += __shfl_xor_sync(0xffffffffu, n[q], o);
    }

    if (slot == 0) {   // lanes o8==0 (half 0) and o8==1 (half 1)
        const float is = 1.0f / s;
        float v[8];
        #pragma unroll
        for (int q = 0; q < 8; q++) v[q] = n[q] * is;

        if (!last) {
            if (store_ok) {
                float4* o4 = (float4*)hout;
                o4[node * 4 + p * 2 + 0] = make_float4(v[0], v[1], v[2], v[3]);
                o4[node * 4 + p * 2 + 1] = make_float4(v[4], v[5], v[6], v[7]);
            }
        } else {
            // fused classify + log_softmax: partial logits over this half
            float lg[C_OUT];
            #pragma unroll
            for (int c = 0; c < C_OUT; c++) {
                float acc = 0.f;
                #pragma unroll
                for (int q = 0; q < 8; q++)
                    acc = fmaf(v[q], W2[c * H_DIM + p * 8 + q], acc);
                lg[c] = acc;
            }
            #pragma unroll
            for (int c = 0; c < C_OUT; c++)
                lg[c] += __shfl_xor_sync(pair_mask, lg[c], 1);
            if (p == 0 && store_ok) {
                #pragma unroll
                for (int c = 0; c < C_OUT; c++) lg[c] += b2[c];
                float mx = lg[0];
                #pragma unroll
                for (int c = 1; c < C_OUT; c++) mx = fmaxf(mx, lg[c]);
                float ssum = 0.f;
                #pragma unroll
                for (int c = 0; c < C_OUT; c++) ssum += __expf(lg[c] - mx);
                const float lse = mx + __logf(ssum);
                #pragma unroll
                for (int c = 0; c < C_OUT; c++) out[node * C_OUT + c] = lg[c] - lse;
            }
        }
    }
}

// ======================= launch ==============================================
extern "C" void kernel_launch(void* const* d_in, const int* in_sizes, int n_in,
                              void* d_out, int out_size)
{
    const float* x     = (const float*)d_in[0];
    const int*   ei    = (const int*)d_in[1];
    const float* W1    = (const float*)d_in[2];
    const float* b1    = (const float*)d_in[3];
    const float* beta2 = (const float*)d_in[4];
    const float* beta3 = (const float*)d_in[5];
    const float* beta4 = (const float*)d_in[6];
    const float* W2    = (const float*)d_in[7];
    const float* b2    = (const float*)d_in[8];
    float* out = (float*)d_out;

    const int N = in_sizes[0] / F_IN;
    const int E = in_sizes[1] / 2;
    const int NC = (N + CHUNK - 1) / CHUNK;

    float *hA, *hB;
    cudaGetSymbolAddress((void**)&hA, g_h0);
    cudaGetSymbolAddress((void**)&hB, g_h1);

    // lin1
    k_lin1<<<(N + 63) / 64, 256>>>(x, W1, b1, hA, N);

    // CSR build
    k_count_init<<<(N + 255) / 256, 256>>>(N);
    k_count<<<((E + 3) / 4 + 255) / 256, 256>>>(ei, E);
    k_csum<<<NC, 256>>>(N);
    k_scan<<<1, 256>>>(NC);
    k_cscan<<<NC, 512>>>(N);
    k_scatter<<<(E + N + 255) / 256, 256>>>(ei, E, N);

    // 4 AGNN layers (layer 0: beta fixed at 1.0; layer 3 fuses classify)
    const float* betas[4] = {nullptr, beta2, beta3, beta4};
    float* cur = hA; float* nxt = hB;
    for (int l = 0; l < 4; l++) {
        const int last = (l == 3);
        k_agnn<<<(N * 8 + 255) / 256, 256>>>(cur, nxt,
                                             betas[l], l > 0 ? 1 : 0, N,
                                             last, W2, b2, out);
        float* t = cur; cur = nxt; nxt = t;
    }
}